// round 15
// baseline (speedup 1.0000x reference)
#include <cuda_runtime.h>
#include <cuda_fp16.h>
#include <cstdint>

#define N_MAX 100000
#define E_MAX 1000000
#define F 64
#define ALPHA 0.2f
#define WPAD 68   // smem W row stride (floats): 272B rows -> 16B-aligned float4, conflict-free

typedef unsigned long long ull;

// Scratch (static __device__ allocation — no cudaMalloc allowed)
// Permuted fp16 Wh: g_Whh[n*32 + l] = (Wh[n][l], Wh[n][l+32]). 12.8 MB, L2-resident.
__device__ __half2 g_Whh[N_MAX * 32];
__device__ float   g_ssrc[N_MAX];
__device__ float   g_sdst[N_MAX];
__device__ int     g_cnt[N_MAX];
__device__ int     g_off[N_MAX];
__device__ int     g_cur[N_MAX];
__device__ int     g_cursor;
__device__ int     g_srcs[E_MAX];       // src indices, dst-grouped (4 MB)

// ---- packed f32x2 helpers (Blackwell FFMA2) --------------------------------
__device__ __forceinline__ ull pack2(float lo, float hi) {
    ull r; asm("mov.b64 %0, {%1, %2};" : "=l"(r) : "f"(lo), "f"(hi)); return r;
}
__device__ __forceinline__ float2 unpack2(ull v) {
    float2 f; asm("mov.b64 {%0, %1}, %2;" : "=f"(f.x), "=f"(f.y) : "l"(v)); return f;
}
__device__ __forceinline__ ull ffma2(ull a, ull b, ull c) {
    ull d; asm("fma.rn.f32x2 %0, %1, %2, %3;" : "=l"(d) : "l"(a), "l"(b), "l"(c)); return d;
}

// ---------------------------------------------------------------------------
// K0: zero counters + global cursor
// ---------------------------------------------------------------------------
__global__ void zero_kernel(int n_nodes) {
    int i = blockIdx.x * blockDim.x + threadIdx.x;
    if (i < n_nodes) g_cnt[i] = 0;
    if (i == 0) g_cursor = 0;
}

// ---------------------------------------------------------------------------
// K1: Wh = h @ W^T + Wb ; scores fused. 8 nodes/warp as 4 node-PAIRS;
// packed f32x2 accumulators via fma.rn.f32x2; h pre-interleaved in smem.
// ---------------------------------------------------------------------------
__global__ void __launch_bounds__(256) wh_kernel(
    const float* __restrict__ h, const float* __restrict__ W,
    const float* __restrict__ Wb, const float* __restrict__ a, int n_nodes)
{
    __shared__ float Wp[F * WPAD];                       // Wp[j*WPAD+k] = W[j][k]
    __shared__ float sWb[F];
    __shared__ float sa[2 * F];
    // hp[warp][pair][k2][j]: j = (hA[2k2], hB[2k2], hA[2k2+1], hB[2k2+1]); 16 KB
    __shared__ __align__(16) float hp[8][4][32][4];

    int tid = threadIdx.x;
    for (int i = tid; i < F * F; i += 256) {
        int j = i >> 6, k = i & 63;
        Wp[j * WPAD + k] = W[i];
    }
    if (tid < F) sWb[tid] = Wb[tid];
    if (tid < 2 * F) sa[tid] = a[tid];

    int warp = tid >> 5;
    int lane = tid & 31;
    int n0 = (blockIdx.x * 8 + warp) * 8;

    #pragma unroll
    for (int j = 0; j < 16; j++) {
        int flat = j * 32 + lane;            // 0..511
        int nl = flat >> 6;                  // local node 0..7
        int k  = flat & 63;
        int n  = min(n0 + nl, n_nodes - 1);
        hp[warp][nl >> 1][k >> 1][(k & 1) * 2 + (nl & 1)] = h[(size_t)n * F + k];
    }
    __syncthreads();
    if (n0 >= n_nodes) return;

    const float4* w0p = reinterpret_cast<const float4*>(&Wp[lane * WPAD]);
    const float4* w1p = reinterpret_cast<const float4*>(&Wp[(lane + 32) * WPAD]);
    const ulonglong2* hp2[4];
    #pragma unroll
    for (int p = 0; p < 4; p++)
        hp2[p] = reinterpret_cast<const ulonglong2*>(&hp[warp][p][0][0]);

    ull acc0[4] = {0ull, 0ull, 0ull, 0ull};   // (nodeA,nodeB) col lane
    ull acc1[4] = {0ull, 0ull, 0ull, 0ull};   // (nodeA,nodeB) col lane+32

    #pragma unroll
    for (int k4 = 0; k4 < 16; k4++) {
        float4 w0 = w0p[k4];
        float4 w1 = w1p[k4];
        ull w0s0 = pack2(w0.x, w0.x), w0s1 = pack2(w0.y, w0.y);
        ull w0s2 = pack2(w0.z, w0.z), w0s3 = pack2(w0.w, w0.w);
        ull w1s0 = pack2(w1.x, w1.x), w1s1 = pack2(w1.y, w1.y);
        ull w1s2 = pack2(w1.z, w1.z), w1s3 = pack2(w1.w, w1.w);
        #pragma unroll
        for (int p = 0; p < 4; p++) {
            ulonglong2 ha = hp2[p][2 * k4];
            ulonglong2 hb = hp2[p][2 * k4 + 1];
            acc0[p] = ffma2(ha.x, w0s0, acc0[p]);
            acc1[p] = ffma2(ha.x, w1s0, acc1[p]);
            acc0[p] = ffma2(ha.y, w0s1, acc0[p]);
            acc1[p] = ffma2(ha.y, w1s1, acc1[p]);
            acc0[p] = ffma2(hb.x, w0s2, acc0[p]);
            acc1[p] = ffma2(hb.x, w1s2, acc1[p]);
            acc0[p] = ffma2(hb.y, w0s3, acc0[p]);
            acc1[p] = ffma2(hb.y, w1s3, acc1[p]);
        }
    }

    float b0 = sWb[lane], b1 = sWb[lane + 32];
    float as0 = sa[lane], as1 = sa[lane + 32];
    float ad0 = sa[F + lane], ad1 = sa[F + lane + 32];

    #pragma unroll
    for (int p = 0; p < 4; p++) {
        float2 a0 = unpack2(acc0[p]);
        float2 a1 = unpack2(acc1[p]);
        #pragma unroll
        for (int w = 0; w < 2; w++) {
            int n = n0 + 2 * p + w;
            if (n >= n_nodes) break;
            float v0 = (w ? a0.y : a0.x) + b0;
            float v1 = (w ? a1.y : a1.x) + b1;
            g_Whh[(size_t)n * 32 + lane] = __floats2half2_rn(v0, v1);

            float pp = v0 * as0 + v1 * as1;
            float qq = v0 * ad0 + v1 * ad1;
            #pragma unroll
            for (int o = 16; o > 0; o >>= 1) {
                pp += __shfl_down_sync(0xffffffffu, pp, o);
                qq += __shfl_down_sync(0xffffffffu, qq, o);
            }
            if (lane == 0) {
                g_ssrc[n] = pp;
                g_sdst[n] = qq;
            }
        }
    }
}

// ---------------------------------------------------------------------------
// K2: count edges per dst
// ---------------------------------------------------------------------------
__global__ void __launch_bounds__(256) count_kernel(
    const int* __restrict__ dst, int n_edges)
{
    int i = blockIdx.x * blockDim.x + threadIdx.x;
    if (i < n_edges) atomicAdd(&g_cnt[dst[i]], 1);
}

// ---------------------------------------------------------------------------
// K3: CSR offsets (1024-thread block scan; ~98 cursor atomics)
// ---------------------------------------------------------------------------
__global__ void __launch_bounds__(1024) offset_kernel(int n_nodes) {
    __shared__ int warp_sums[32];
    __shared__ int block_base;

    int i = blockIdx.x * 1024 + threadIdx.x;
    int lane = threadIdx.x & 31;
    int wid  = threadIdx.x >> 5;
    int c = (i < n_nodes) ? g_cnt[i] : 0;

    int s = c;
    #pragma unroll
    for (int o = 1; o < 32; o <<= 1) {
        int t = __shfl_up_sync(0xffffffffu, s, o);
        if (lane >= o) s += t;
    }
    if (lane == 31) warp_sums[wid] = s;
    __syncthreads();

    if (wid == 0) {
        int v = warp_sums[lane];
        int sv = v;
        #pragma unroll
        for (int o = 1; o < 32; o <<= 1) {
            int t = __shfl_up_sync(0xffffffffu, sv, o);
            if (lane >= o) sv += t;
        }
        warp_sums[lane] = sv - v;
        if (lane == 31) block_base = atomicAdd(&g_cursor, sv);
    }
    __syncthreads();

    if (i < n_nodes) {
        int off = block_base + warp_sums[wid] + (s - c);
        g_off[i] = off;
        g_cur[i] = off;
    }
}

// ---------------------------------------------------------------------------
// K4: scatter — NO scores needed: just bucket src by dst. Runs on the side
// stream, fully hidden under wh. Slot order arbitrary; per-dst set fixed.
// ---------------------------------------------------------------------------
__global__ void __launch_bounds__(256) scatter_kernel(
    const int* __restrict__ src, const int* __restrict__ dst, int n_edges)
{
    int i = blockIdx.x * blockDim.x + threadIdx.x;
    if (i >= n_edges) return;
    int pos = atomicAdd(&g_cur[dst[i]], 1);
    g_srcs[pos] = src[i];
}

// ---------------------------------------------------------------------------
// K5: gather — one warp per dst node. Staging lanes compute ex inline
// (dst == gwarp, so sdst+ab is a warp constant; ssrc[s] is an L2-hot 4B load;
// exp once per edge). Inner loop: 4 edges/iter, quarter-warp rows, smem
// record multicast. Max-shift skipped (cancels exactly in attn).
// ---------------------------------------------------------------------------
__global__ void __launch_bounds__(256) gather_kernel(
    const float* __restrict__ ab_p, float* __restrict__ out, int n_nodes)
{
    __shared__ int2 s_rec[8][32];

    int warp = threadIdx.x >> 5;
    int gwarp = (blockIdx.x * blockDim.x + threadIdx.x) >> 5;
    int lane = threadIdx.x & 31;
    if (gwarp >= n_nodes) return;

    int beg = g_off[gwarp];
    int cnt = g_cnt[gwarp];
    int qtr = lane >> 3;            // which edge within the group of 4
    int l8  = lane & 7;             // 16B slot within the row

    float sdst_ab = g_sdst[gwarp] + __ldg(ab_p);   // warp-constant

    const float4* whh4 = reinterpret_cast<const float4*>(g_Whh);
    float acc[8] = {0.f, 0.f, 0.f, 0.f, 0.f, 0.f, 0.f, 0.f};
    float den = 0.0f;

    for (int base = 0; base < cnt; base += 32) {
        int idx = base + lane;
        int sld = 0;
        float ex = 0.0f;
        if (idx < cnt) {
            sld = __ldg(&g_srcs[beg + idx]);
            float x = __ldg(&g_ssrc[sld]) + sdst_ab;
            x = (x > 0.0f) ? x : ALPHA * x;
            ex = expf(x);
        }
        s_rec[warp][lane] = make_int2(sld, __float_as_int(ex));
        __syncwarp();
        int m = min(cnt - base, 32);
        int iters = (m + 3) >> 2;
        #pragma unroll 4
        for (int k = 0; k < iters; k++) {
            int2 rec = s_rec[warp][4 * k + qtr];   // multicast LDS.64
            int   s  = rec.x;
            float exk = __int_as_float(rec.y);
            float4 w = __ldg(&whh4[(size_t)s * 8 + l8]);   // 4 half2
            float2 f0 = __half22float2(*reinterpret_cast<__half2*>(&w.x));
            float2 f1 = __half22float2(*reinterpret_cast<__half2*>(&w.y));
            float2 f2 = __half22float2(*reinterpret_cast<__half2*>(&w.z));
            float2 f3 = __half22float2(*reinterpret_cast<__half2*>(&w.w));
            acc[0] = fmaf(exk, f0.x, acc[0]);   // col 4l8+0
            acc[1] = fmaf(exk, f0.y, acc[1]);   // col 4l8+32
            acc[2] = fmaf(exk, f1.x, acc[2]);   // col 4l8+1
            acc[3] = fmaf(exk, f1.y, acc[3]);   // col 4l8+33
            acc[4] = fmaf(exk, f2.x, acc[4]);   // col 4l8+2
            acc[5] = fmaf(exk, f2.y, acc[5]);   // col 4l8+34
            acc[6] = fmaf(exk, f3.x, acc[6]);   // col 4l8+3
            acc[7] = fmaf(exk, f3.y, acc[7]);   // col 4l8+35
            den += exk;
        }
        __syncwarp();
    }

    // combine the four quarters (same l8 slot across quarters)
    #pragma unroll
    for (int j = 0; j < 8; j++) {
        acc[j] += __shfl_xor_sync(0xffffffffu, acc[j], 8);
        acc[j] += __shfl_xor_sync(0xffffffffu, acc[j], 16);
    }
    den += __shfl_xor_sync(0xffffffffu, den, 8);
    den += __shfl_xor_sync(0xffffffffu, den, 16);

    if (qtr == 0) {
        float r = (den > 0.0f) ? (1.0f / den) : 1.0f;  // cnt==0 -> acc==0 == ref
        float4 lo = make_float4(acc[0] * r, acc[2] * r, acc[4] * r, acc[6] * r);
        float4 hi = make_float4(acc[1] * r, acc[3] * r, acc[5] * r, acc[7] * r);
        float4* op = reinterpret_cast<float4*>(out) + (size_t)gwarp * 16;
        op[l8]     = lo;
        op[l8 + 8] = hi;
    }
}

// ---------------------------------------------------------------------------
extern "C" void kernel_launch(void* const* d_in, const int* in_sizes, int n_in,
                              void* d_out, int out_size) {
    const float* h   = (const float*)d_in[0];
    const float* W   = (const float*)d_in[1];
    const float* Wb  = (const float*)d_in[2];
    const float* a   = (const float*)d_in[3];
    const float* ab  = (const float*)d_in[4];
    const int*   src = (const int*)d_in[5];
    const int*   dst = (const int*)d_in[6];
    float* out = (float*)d_out;

    int n_nodes = in_sizes[0] / F;
    int n_edges = in_sizes[5];

    static cudaStream_t side = nullptr;
    static cudaEvent_t evFork = nullptr, evJoin = nullptr;
    if (!side) {
        cudaStreamCreateWithFlags(&side, cudaStreamNonBlocking);
        cudaEventCreateWithFlags(&evFork, cudaEventDisableTiming);
        cudaEventCreateWithFlags(&evJoin, cudaEventDisableTiming);
    }

    // Side stream: full CSR build INCLUDING scatter (no score dependency)
    // — hidden under the wh GEMM on the main stream.
    cudaEventRecord(evFork, 0);
    cudaStreamWaitEvent(side, evFork, 0);

    zero_kernel<<<(n_nodes + 255) / 256, 256, 0, side>>>(n_nodes);
    count_kernel<<<(n_edges + 255) / 256, 256, 0, side>>>(dst, n_edges);
    offset_kernel<<<(n_nodes + 1023) / 1024, 1024, 0, side>>>(n_nodes);
    scatter_kernel<<<(n_edges + 255) / 256, 256, 0, side>>>(src, dst, n_edges);
    cudaEventRecord(evJoin, side);

    wh_kernel<<<(n_nodes + 63) / 64, 256>>>(h, W, Wb, a, n_nodes);

    // Gather needs wh (main) + CSR/scatter (side).
    cudaStreamWaitEvent(0, evJoin, 0);
    gather_kernel<<<(n_nodes + 7) / 8, 256>>>(ab, out, n_nodes);
}

// round 16
// speedup vs baseline: 1.1499x; 1.1499x over previous
#include <cuda_runtime.h>
#include <cuda_fp16.h>
#include <cstdint>

#define N_MAX 100000
#define E_MAX 1000000
#define F 64
#define ALPHA 0.2f
#define WPAD 68   // smem W row stride (floats): 272B rows -> 16B-aligned float4, conflict-free

typedef unsigned long long ull;

// Scratch (static __device__ allocation — no cudaMalloc allowed)
// Permuted fp16 Wh: g_Whh[n*32 + l] = (Wh[n][l], Wh[n][l+32]). 12.8 MB, L2-resident.
__device__ __half2 g_Whh[N_MAX * 32];
__device__ float   g_ssrc[N_MAX];
__device__ float   g_sdst[N_MAX];
__device__ int     g_cnt[N_MAX];
__device__ int     g_off[N_MAX];
__device__ int     g_cur[N_MAX];
__device__ int     g_cursor;
__device__ int     g_srcs[E_MAX];       // src indices, dst-grouped (4 MB)

// ---- packed f32x2 helpers (Blackwell FFMA2) --------------------------------
__device__ __forceinline__ ull pack2(float lo, float hi) {
    ull r; asm("mov.b64 %0, {%1, %2};" : "=l"(r) : "f"(lo), "f"(hi)); return r;
}
__device__ __forceinline__ float2 unpack2(ull v) {
    float2 f; asm("mov.b64 {%0, %1}, %2;" : "=f"(f.x), "=f"(f.y) : "l"(v)); return f;
}
__device__ __forceinline__ ull ffma2(ull a, ull b, ull c) {
    ull d; asm("fma.rn.f32x2 %0, %1, %2, %3;" : "=l"(d) : "l"(a), "l"(b), "l"(c)); return d;
}

// ---------------------------------------------------------------------------
// K0: zero counters + global cursor
// ---------------------------------------------------------------------------
__global__ void zero_kernel(int n_nodes) {
    int i = blockIdx.x * blockDim.x + threadIdx.x;
    if (i < n_nodes) g_cnt[i] = 0;
    if (i == 0) g_cursor = 0;
}

// ---------------------------------------------------------------------------
// K1: Wh = h @ W^T + Wb ; scores fused. 8 nodes/warp as 4 node-PAIRS;
// packed f32x2 accumulators via fma.rn.f32x2; h pre-interleaved in smem.
// ---------------------------------------------------------------------------
__global__ void __launch_bounds__(256) wh_kernel(
    const float* __restrict__ h, const float* __restrict__ W,
    const float* __restrict__ Wb, const float* __restrict__ a, int n_nodes)
{
    __shared__ float Wp[F * WPAD];                       // Wp[j*WPAD+k] = W[j][k]
    __shared__ float sWb[F];
    __shared__ float sa[2 * F];
    // hp[warp][pair][k2][j]: j = (hA[2k2], hB[2k2], hA[2k2+1], hB[2k2+1]); 16 KB
    __shared__ __align__(16) float hp[8][4][32][4];

    int tid = threadIdx.x;
    for (int i = tid; i < F * F; i += 256) {
        int j = i >> 6, k = i & 63;
        Wp[j * WPAD + k] = W[i];
    }
    if (tid < F) sWb[tid] = Wb[tid];
    if (tid < 2 * F) sa[tid] = a[tid];

    int warp = tid >> 5;
    int lane = tid & 31;
    int n0 = (blockIdx.x * 8 + warp) * 8;

    #pragma unroll
    for (int j = 0; j < 16; j++) {
        int flat = j * 32 + lane;            // 0..511
        int nl = flat >> 6;                  // local node 0..7
        int k  = flat & 63;
        int n  = min(n0 + nl, n_nodes - 1);
        hp[warp][nl >> 1][k >> 1][(k & 1) * 2 + (nl & 1)] = h[(size_t)n * F + k];
    }
    __syncthreads();
    if (n0 >= n_nodes) return;

    const float4* w0p = reinterpret_cast<const float4*>(&Wp[lane * WPAD]);
    const float4* w1p = reinterpret_cast<const float4*>(&Wp[(lane + 32) * WPAD]);
    const ulonglong2* hp2[4];
    #pragma unroll
    for (int p = 0; p < 4; p++)
        hp2[p] = reinterpret_cast<const ulonglong2*>(&hp[warp][p][0][0]);

    ull acc0[4] = {0ull, 0ull, 0ull, 0ull};   // (nodeA,nodeB) col lane
    ull acc1[4] = {0ull, 0ull, 0ull, 0ull};   // (nodeA,nodeB) col lane+32

    #pragma unroll
    for (int k4 = 0; k4 < 16; k4++) {
        float4 w0 = w0p[k4];
        float4 w1 = w1p[k4];
        ull w0s0 = pack2(w0.x, w0.x), w0s1 = pack2(w0.y, w0.y);
        ull w0s2 = pack2(w0.z, w0.z), w0s3 = pack2(w0.w, w0.w);
        ull w1s0 = pack2(w1.x, w1.x), w1s1 = pack2(w1.y, w1.y);
        ull w1s2 = pack2(w1.z, w1.z), w1s3 = pack2(w1.w, w1.w);
        #pragma unroll
        for (int p = 0; p < 4; p++) {
            ulonglong2 ha = hp2[p][2 * k4];
            ulonglong2 hb = hp2[p][2 * k4 + 1];
            acc0[p] = ffma2(ha.x, w0s0, acc0[p]);
            acc1[p] = ffma2(ha.x, w1s0, acc1[p]);
            acc0[p] = ffma2(ha.y, w0s1, acc0[p]);
            acc1[p] = ffma2(ha.y, w1s1, acc1[p]);
            acc0[p] = ffma2(hb.x, w0s2, acc0[p]);
            acc1[p] = ffma2(hb.x, w1s2, acc1[p]);
            acc0[p] = ffma2(hb.y, w0s3, acc0[p]);
            acc1[p] = ffma2(hb.y, w1s3, acc1[p]);
        }
    }

    float b0 = sWb[lane], b1 = sWb[lane + 32];
    float as0 = sa[lane], as1 = sa[lane + 32];
    float ad0 = sa[F + lane], ad1 = sa[F + lane + 32];

    #pragma unroll
    for (int p = 0; p < 4; p++) {
        float2 a0 = unpack2(acc0[p]);
        float2 a1 = unpack2(acc1[p]);
        #pragma unroll
        for (int w = 0; w < 2; w++) {
            int n = n0 + 2 * p + w;
            if (n >= n_nodes) break;
            float v0 = (w ? a0.y : a0.x) + b0;
            float v1 = (w ? a1.y : a1.x) + b1;
            g_Whh[(size_t)n * 32 + lane] = __floats2half2_rn(v0, v1);

            float pp = v0 * as0 + v1 * as1;
            float qq = v0 * ad0 + v1 * ad1;
            #pragma unroll
            for (int o = 16; o > 0; o >>= 1) {
                pp += __shfl_down_sync(0xffffffffu, pp, o);
                qq += __shfl_down_sync(0xffffffffu, qq, o);
            }
            if (lane == 0) {
                g_ssrc[n] = pp;
                g_sdst[n] = qq;
            }
        }
    }
}

// ---------------------------------------------------------------------------
// K2: count edges per dst
// ---------------------------------------------------------------------------
__global__ void __launch_bounds__(256) count_kernel(
    const int* __restrict__ dst, int n_edges)
{
    int i = blockIdx.x * blockDim.x + threadIdx.x;
    if (i < n_edges) atomicAdd(&g_cnt[dst[i]], 1);
}

// ---------------------------------------------------------------------------
// K3: CSR offsets (1024-thread block scan; ~98 cursor atomics)
// ---------------------------------------------------------------------------
__global__ void __launch_bounds__(1024) offset_kernel(int n_nodes) {
    __shared__ int warp_sums[32];
    __shared__ int block_base;

    int i = blockIdx.x * 1024 + threadIdx.x;
    int lane = threadIdx.x & 31;
    int wid  = threadIdx.x >> 5;
    int c = (i < n_nodes) ? g_cnt[i] : 0;

    int s = c;
    #pragma unroll
    for (int o = 1; o < 32; o <<= 1) {
        int t = __shfl_up_sync(0xffffffffu, s, o);
        if (lane >= o) s += t;
    }
    if (lane == 31) warp_sums[wid] = s;
    __syncthreads();

    if (wid == 0) {
        int v = warp_sums[lane];
        int sv = v;
        #pragma unroll
        for (int o = 1; o < 32; o <<= 1) {
            int t = __shfl_up_sync(0xffffffffu, sv, o);
            if (lane >= o) sv += t;
        }
        warp_sums[lane] = sv - v;
        if (lane == 31) block_base = atomicAdd(&g_cursor, sv);
    }
    __syncthreads();

    if (i < n_nodes) {
        int off = block_base + warp_sums[wid] + (s - c);
        g_off[i] = off;
        g_cur[i] = off;
    }
}

// ---------------------------------------------------------------------------
// K4: scatter — bucket src by dst (no scores needed; side stream, hidden).
// ---------------------------------------------------------------------------
__global__ void __launch_bounds__(256) scatter_kernel(
    const int* __restrict__ src, const int* __restrict__ dst, int n_edges)
{
    int i = blockIdx.x * blockDim.x + threadIdx.x;
    if (i >= n_edges) return;
    int pos = atomicAdd(&g_cur[dst[i]], 1);
    g_srcs[pos] = src[i];
}

// ---------------------------------------------------------------------------
// K5: gather v2 — QUARTER-WARP (8 lanes) per node; 4 independent nodes/warp.
// Each lane covers the full fp16 row (8 x 16B): no staging, no syncwarp,
// no cross-lane reduction. src/ssrc loads are same-address broadcasts; den
// accumulated redundantly per lane. Main loop 4-wide for MLP. Avg degree 10
// -> per-node fixed cost is tiny. Max-shift skipped (cancels in attn).
// ---------------------------------------------------------------------------
__global__ void __launch_bounds__(256) gather_kernel(
    const float* __restrict__ ab_p, float* __restrict__ out, int n_nodes)
{
    int node = (blockIdx.x * blockDim.x + threadIdx.x) >> 3;
    int l8   = threadIdx.x & 7;
    if (node >= n_nodes) return;

    int beg = g_off[node];
    int cnt = g_cnt[node];
    float sdst_ab = g_sdst[node] + __ldg(ab_p);

    const float4* whh4 = reinterpret_cast<const float4*>(g_Whh);
    float acc[8] = {0.f, 0.f, 0.f, 0.f, 0.f, 0.f, 0.f, 0.f};
    float den = 0.0f;

    int e = 0;
    // 4-wide main loop: batched loads give MLP>=4 on the L2 chain
    for (; e + 4 <= cnt; e += 4) {
        int s0 = __ldg(&g_srcs[beg + e]);
        int s1 = __ldg(&g_srcs[beg + e + 1]);
        int s2 = __ldg(&g_srcs[beg + e + 2]);
        int s3 = __ldg(&g_srcs[beg + e + 3]);
        float x0 = __ldg(&g_ssrc[s0]) + sdst_ab;
        float x1 = __ldg(&g_ssrc[s1]) + sdst_ab;
        float x2 = __ldg(&g_ssrc[s2]) + sdst_ab;
        float x3 = __ldg(&g_ssrc[s3]) + sdst_ab;
        float4 w0 = __ldg(&whh4[(size_t)s0 * 8 + l8]);
        float4 w1 = __ldg(&whh4[(size_t)s1 * 8 + l8]);
        float4 w2 = __ldg(&whh4[(size_t)s2 * 8 + l8]);
        float4 w3 = __ldg(&whh4[(size_t)s3 * 8 + l8]);
        x0 = (x0 > 0.f) ? x0 : ALPHA * x0;  float ex0 = __expf(x0);
        x1 = (x1 > 0.f) ? x1 : ALPHA * x1;  float ex1 = __expf(x1);
        x2 = (x2 > 0.f) ? x2 : ALPHA * x2;  float ex2 = __expf(x2);
        x3 = (x3 > 0.f) ? x3 : ALPHA * x3;  float ex3 = __expf(x3);
        den += (ex0 + ex1) + (ex2 + ex3);
        #pragma unroll
        for (int j = 0; j < 4; j++) {
            float ex; float4 w;
            if (j == 0) { ex = ex0; w = w0; }
            else if (j == 1) { ex = ex1; w = w1; }
            else if (j == 2) { ex = ex2; w = w2; }
            else { ex = ex3; w = w3; }
            float2 f0 = __half22float2(*reinterpret_cast<__half2*>(&w.x));
            float2 f1 = __half22float2(*reinterpret_cast<__half2*>(&w.y));
            float2 f2 = __half22float2(*reinterpret_cast<__half2*>(&w.z));
            float2 f3 = __half22float2(*reinterpret_cast<__half2*>(&w.w));
            acc[0] = fmaf(ex, f0.x, acc[0]);
            acc[1] = fmaf(ex, f0.y, acc[1]);
            acc[2] = fmaf(ex, f1.x, acc[2]);
            acc[3] = fmaf(ex, f1.y, acc[3]);
            acc[4] = fmaf(ex, f2.x, acc[4]);
            acc[5] = fmaf(ex, f2.y, acc[5]);
            acc[6] = fmaf(ex, f3.x, acc[6]);
            acc[7] = fmaf(ex, f3.y, acc[7]);
        }
    }
    for (; e < cnt; e++) {
        int s = __ldg(&g_srcs[beg + e]);
        float x = __ldg(&g_ssrc[s]) + sdst_ab;
        float4 w = __ldg(&whh4[(size_t)s * 8 + l8]);
        x = (x > 0.f) ? x : ALPHA * x;
        float ex = __expf(x);
        den += ex;
        float2 f0 = __half22float2(*reinterpret_cast<__half2*>(&w.x));
        float2 f1 = __half22float2(*reinterpret_cast<__half2*>(&w.y));
        float2 f2 = __half22float2(*reinterpret_cast<__half2*>(&w.z));
        float2 f3 = __half22float2(*reinterpret_cast<__half2*>(&w.w));
        acc[0] = fmaf(ex, f0.x, acc[0]);
        acc[1] = fmaf(ex, f0.y, acc[1]);
        acc[2] = fmaf(ex, f1.x, acc[2]);
        acc[3] = fmaf(ex, f1.y, acc[3]);
        acc[4] = fmaf(ex, f2.x, acc[4]);
        acc[5] = fmaf(ex, f2.y, acc[5]);
        acc[6] = fmaf(ex, f3.x, acc[6]);
        acc[7] = fmaf(ex, f3.y, acc[7]);
    }

    float r = (den > 0.0f) ? (1.0f / den) : 1.0f;   // cnt==0 -> acc==0 == ref
    // lane l8 holds cols {4l8..4l8+3} (even slots) and {32+4l8..35+4l8} (odd)
    float4 lo = make_float4(acc[0] * r, acc[2] * r, acc[4] * r, acc[6] * r);
    float4 hi = make_float4(acc[1] * r, acc[3] * r, acc[5] * r, acc[7] * r);
    float4* op = reinterpret_cast<float4*>(out) + (size_t)node * 16;
    op[l8]     = lo;
    op[l8 + 8] = hi;
}

// ---------------------------------------------------------------------------
extern "C" void kernel_launch(void* const* d_in, const int* in_sizes, int n_in,
                              void* d_out, int out_size) {
    const float* h   = (const float*)d_in[0];
    const float* W   = (const float*)d_in[1];
    const float* Wb  = (const float*)d_in[2];
    const float* a   = (const float*)d_in[3];
    const float* ab  = (const float*)d_in[4];
    const int*   src = (const int*)d_in[5];
    const int*   dst = (const int*)d_in[6];
    float* out = (float*)d_out;

    int n_nodes = in_sizes[0] / F;
    int n_edges = in_sizes[5];

    static cudaStream_t side = nullptr;
    static cudaEvent_t evFork = nullptr, evJoin = nullptr;
    if (!side) {
        cudaStreamCreateWithFlags(&side, cudaStreamNonBlocking);
        cudaEventCreateWithFlags(&evFork, cudaEventDisableTiming);
        cudaEventCreateWithFlags(&evJoin, cudaEventDisableTiming);
    }

    // Side stream: full CSR build incl. scatter — hidden under wh.
    cudaEventRecord(evFork, 0);
    cudaStreamWaitEvent(side, evFork, 0);

    zero_kernel<<<(n_nodes + 255) / 256, 256, 0, side>>>(n_nodes);
    count_kernel<<<(n_edges + 255) / 256, 256, 0, side>>>(dst, n_edges);
    offset_kernel<<<(n_nodes + 1023) / 1024, 1024, 0, side>>>(n_nodes);
    scatter_kernel<<<(n_edges + 255) / 256, 256, 0, side>>>(src, dst, n_edges);
    cudaEventRecord(evJoin, side);

    wh_kernel<<<(n_nodes + 63) / 64, 256>>>(h, W, Wb, a, n_nodes);

    // Gather needs wh (main) + CSR/scatter (side).
    cudaStreamWaitEvent(0, evJoin, 0);
    gather_kernel<<<(n_nodes * 8 + 255) / 256, 256>>>(ab, out, n_nodes);
}

// round 17
// speedup vs baseline: 1.3407x; 1.1659x over previous
#include <cuda_runtime.h>
#include <cuda_fp16.h>
#include <mma.h>
#include <cstdint>

using namespace nvcuda;

#define N_MAX 100000
#define E_MAX 1000000
#define F 64
#define ALPHA 0.2f
#define LDH 72   // half stride (multiple of 8): conflict-benign, 32B-aligned tiles
#define LDO 68   // float stride (multiple of 4) for fp32 output staging

// Scratch (static __device__ allocation — no cudaMalloc allowed)
// Permuted fp16 Wh: g_Whh[n*32 + l] = (Wh[n][l], Wh[n][l+32]). 12.8 MB, L2-resident.
__device__ __half2 g_Whh[N_MAX * 32];
__device__ float   g_ssrc[N_MAX];
__device__ float   g_sdst[N_MAX];
__device__ int     g_cnt[N_MAX];
__device__ int     g_off[N_MAX];
__device__ int     g_cur[N_MAX];
__device__ int     g_cursor;
__device__ int     g_srcs[E_MAX];       // src indices, dst-grouped (4 MB)

// ---------------------------------------------------------------------------
// K1: Wh = h @ W^T + Wb via fp16 HMMA (wmma m16n16k16, fp32 accumulate);
// scores fused from the fp32 staging tile. Block = 128 nodes, 8 warps;
// warp w owns rows 16w..16w+15 x all 64 cols (4 n-tiles), k = 4 x 16.
// smem: A/B fp16 tiles unioned with the fp32 output staging (<48KB static).
// ---------------------------------------------------------------------------
__global__ void __launch_bounds__(256) wh_kernel(
    const float* __restrict__ h, const float* __restrict__ W,
    const float* __restrict__ Wb, const float* __restrict__ a, int n_nodes)
{
    // buf layout phase 1: hA[128*LDH] halves, then wB[64*LDH] halves (27648 B)
    //            phase 2: outS[128*LDO] floats (34816 B)
    __shared__ __align__(32) char buf[128 * LDO * 4];
    __shared__ float sWb[F];
    __shared__ float sa[2 * F];

    __half* hA = reinterpret_cast<__half*>(buf);
    __half* wB = reinterpret_cast<__half*>(buf + 128 * LDH * 2);
    float*  outS = reinterpret_cast<float*>(buf);

    int tid = threadIdx.x;
    int m0 = blockIdx.x * 128;

    // stage W (row j, col k) as fp16 at wB[j*LDH + k]  (B col-major: B(k,j)=W[j][k])
    for (int i = tid; i < F * F; i += 256) {
        int j = i >> 6, k = i & 63;
        wB[j * LDH + k] = __float2half(W[i]);
    }
    if (tid < F) sWb[tid] = Wb[tid];
    if (tid < 2 * F) sa[tid] = a[tid];

    // stage h rows (clamped) as fp16
    for (int i4 = tid; i4 < 128 * 16; i4 += 256) {
        int r = i4 >> 4, c4 = i4 & 15;
        int n = min(m0 + r, n_nodes - 1);
        float4 v = __ldg(reinterpret_cast<const float4*>(&h[(size_t)n * F + c4 * 4]));
        __half2* d = reinterpret_cast<__half2*>(&hA[r * LDH + c4 * 4]);
        d[0] = __floats2half2_rn(v.x, v.y);
        d[1] = __floats2half2_rn(v.z, v.w);
    }
    __syncthreads();

    int warp = tid >> 5;
    int lane = tid & 31;

    wmma::fragment<wmma::accumulator, 16, 16, 16, float> dacc[4];
    #pragma unroll
    for (int nn = 0; nn < 4; nn++) wmma::fill_fragment(dacc[nn], 0.0f);

    #pragma unroll
    for (int kk = 0; kk < 4; kk++) {
        wmma::fragment<wmma::matrix_a, 16, 16, 16, __half, wmma::row_major> fa;
        wmma::load_matrix_sync(fa, hA + (warp * 16) * LDH + kk * 16, LDH);
        #pragma unroll
        for (int nn = 0; nn < 4; nn++) {
            wmma::fragment<wmma::matrix_b, 16, 16, 16, __half, wmma::col_major> fb;
            wmma::load_matrix_sync(fb, wB + (nn * 16) * LDH + kk * 16, LDH);
            wmma::mma_sync(dacc[nn], fa, fb, dacc[nn]);
        }
    }
    __syncthreads();   // A/B tiles dead; reuse buf as fp32 staging

    #pragma unroll
    for (int nn = 0; nn < 4; nn++)
        wmma::store_matrix_sync(outS + (warp * 16) * LDO + nn * 16, dacc[nn],
                                LDO, wmma::mem_row_major);
    __syncthreads();

    // Epilogue: bias, permuted half2 pack, fused scores (warp owns 16 rows)
    float b0 = sWb[lane], b1 = sWb[lane + 32];
    float as0 = sa[lane], as1 = sa[lane + 32];
    float ad0 = sa[F + lane], ad1 = sa[F + lane + 32];

    #pragma unroll
    for (int rr = 0; rr < 16; rr++) {
        int r = warp * 16 + rr;
        int n = m0 + r;
        if (n >= n_nodes) break;
        float v0 = outS[r * LDO + lane] + b0;
        float v1 = outS[r * LDO + lane + 32] + b1;
        g_Whh[(size_t)n * 32 + lane] = __floats2half2_rn(v0, v1);

        float pp = v0 * as0 + v1 * as1;
        float qq = v0 * ad0 + v1 * ad1;
        #pragma unroll
        for (int o = 16; o > 0; o >>= 1) {
            pp += __shfl_down_sync(0xffffffffu, pp, o);
            qq += __shfl_down_sync(0xffffffffu, qq, o);
        }
        if (lane == 0) {
            g_ssrc[n] = pp;
            g_sdst[n] = qq;
        }
    }
}

// ---------------------------------------------------------------------------
// K2: count edges per dst (+ zero the CSR cursor for this replay)
// ---------------------------------------------------------------------------
__global__ void __launch_bounds__(256) count_kernel(
    const int* __restrict__ dst, int n_edges)
{
    int i = blockIdx.x * blockDim.x + threadIdx.x;
    if (i == 0) g_cursor = 0;                  // consumed by offset_kernel (later)
    if (i < n_edges) atomicAdd(&g_cnt[dst[i]], 1);
}

// ---------------------------------------------------------------------------
// K3: CSR offsets (1024-thread block scan; ~98 cursor atomics)
// ---------------------------------------------------------------------------
__global__ void __launch_bounds__(1024) offset_kernel(int n_nodes) {
    __shared__ int warp_sums[32];
    __shared__ int block_base;

    int i = blockIdx.x * 1024 + threadIdx.x;
    int lane = threadIdx.x & 31;
    int wid  = threadIdx.x >> 5;
    int c = (i < n_nodes) ? g_cnt[i] : 0;

    int s = c;
    #pragma unroll
    for (int o = 1; o < 32; o <<= 1) {
        int t = __shfl_up_sync(0xffffffffu, s, o);
        if (lane >= o) s += t;
    }
    if (lane == 31) warp_sums[wid] = s;
    __syncthreads();

    if (wid == 0) {
        int v = warp_sums[lane];
        int sv = v;
        #pragma unroll
        for (int o = 1; o < 32; o <<= 1) {
            int t = __shfl_up_sync(0xffffffffu, sv, o);
            if (lane >= o) sv += t;
        }
        warp_sums[lane] = sv - v;
        if (lane == 31) block_base = atomicAdd(&g_cursor, sv);
    }
    __syncthreads();

    if (i < n_nodes) {
        int off = block_base + warp_sums[wid] + (s - c);
        g_off[i] = off;
        g_cur[i] = off;
    }
}

// ---------------------------------------------------------------------------
// K4: scatter — bucket src by dst (no scores needed; side stream, hidden).
// ---------------------------------------------------------------------------
__global__ void __launch_bounds__(256) scatter_kernel(
    const int* __restrict__ src, const int* __restrict__ dst, int n_edges)
{
    int i = blockIdx.x * blockDim.x + threadIdx.x;
    if (i >= n_edges) return;
    int pos = atomicAdd(&g_cur[dst[i]], 1);
    g_srcs[pos] = src[i];
}

// ---------------------------------------------------------------------------
// K5: gather — quarter-warp (8 lanes) per node; fully predicated 4-wide loop
// (no scalar tail: clamped indices, ex zeroed when invalid) so every node
// runs only batched MLP-4 iterations. Max-shift skipped (cancels in attn).
// ---------------------------------------------------------------------------
__global__ void __launch_bounds__(256) gather_kernel(
    const float* __restrict__ ab_p, float* __restrict__ out, int n_nodes)
{
    int node = (blockIdx.x * blockDim.x + threadIdx.x) >> 3;
    int l8   = threadIdx.x & 7;
    if (node >= n_nodes) return;

    int beg = g_off[node];
    int cnt = g_cnt[node];
    float sdst_ab = g_sdst[node] + __ldg(ab_p);

    const float4* whh4 = reinterpret_cast<const float4*>(g_Whh);
    float acc[8] = {0.f, 0.f, 0.f, 0.f, 0.f, 0.f, 0.f, 0.f};
    float den = 0.0f;

    int c = cnt - 1;
    for (int e = 0; e < cnt; e += 4) {
        int i0 = beg + e;
        int i1 = beg + min(e + 1, c);
        int i2 = beg + min(e + 2, c);
        int i3 = beg + min(e + 3, c);
        int s0 = __ldg(&g_srcs[i0]);
        int s1 = __ldg(&g_srcs[i1]);
        int s2 = __ldg(&g_srcs[i2]);
        int s3 = __ldg(&g_srcs[i3]);
        float x0 = __ldg(&g_ssrc[s0]) + sdst_ab;
        float x1 = __ldg(&g_ssrc[s1]) + sdst_ab;
        float x2 = __ldg(&g_ssrc[s2]) + sdst_ab;
        float x3 = __ldg(&g_ssrc[s3]) + sdst_ab;
        float4 w0 = __ldg(&whh4[(size_t)s0 * 8 + l8]);
        float4 w1 = __ldg(&whh4[(size_t)s1 * 8 + l8]);
        float4 w2 = __ldg(&whh4[(size_t)s2 * 8 + l8]);
        float4 w3 = __ldg(&whh4[(size_t)s3 * 8 + l8]);
        x0 = (x0 > 0.f) ? x0 : ALPHA * x0;  float ex0 = __expf(x0);
        x1 = (x1 > 0.f) ? x1 : ALPHA * x1;  float ex1 = __expf(x1);
        x2 = (x2 > 0.f) ? x2 : ALPHA * x2;  float ex2 = __expf(x2);
        x3 = (x3 > 0.f) ? x3 : ALPHA * x3;  float ex3 = __expf(x3);
        ex1 = (e + 1 <= c) ? ex1 : 0.f;
        ex2 = (e + 2 <= c) ? ex2 : 0.f;
        ex3 = (e + 3 <= c) ? ex3 : 0.f;
        den += (ex0 + ex1) + (ex2 + ex3);
        #pragma unroll
        for (int j = 0; j < 4; j++) {
            float ex; float4 w;
            if (j == 0) { ex = ex0; w = w0; }
            else if (j == 1) { ex = ex1; w = w1; }
            else if (j == 2) { ex = ex2; w = w2; }
            else { ex = ex3; w = w3; }
            float2 f0 = __half22float2(*reinterpret_cast<__half2*>(&w.x));
            float2 f1 = __half22float2(*reinterpret_cast<__half2*>(&w.y));
            float2 f2 = __half22float2(*reinterpret_cast<__half2*>(&w.z));
            float2 f3 = __half22float2(*reinterpret_cast<__half2*>(&w.w));
            acc[0] = fmaf(ex, f0.x, acc[0]);
            acc[1] = fmaf(ex, f0.y, acc[1]);
            acc[2] = fmaf(ex, f1.x, acc[2]);
            acc[3] = fmaf(ex, f1.y, acc[3]);
            acc[4] = fmaf(ex, f2.x, acc[4]);
            acc[5] = fmaf(ex, f2.y, acc[5]);
            acc[6] = fmaf(ex, f3.x, acc[6]);
            acc[7] = fmaf(ex, f3.y, acc[7]);
        }
    }

    float r = (den > 0.0f) ? (1.0f / den) : 1.0f;   // cnt==0 -> acc==0 == ref
    // lane l8 holds cols {4l8..4l8+3} (even slots) and {32+4l8..35+4l8} (odd)
    float4 lo = make_float4(acc[0] * r, acc[2] * r, acc[4] * r, acc[6] * r);
    float4 hi = make_float4(acc[1] * r, acc[3] * r, acc[5] * r, acc[7] * r);
    float4* op = reinterpret_cast<float4*>(out) + (size_t)node * 16;
    op[l8]     = lo;
    op[l8 + 8] = hi;
}

// ---------------------------------------------------------------------------
extern "C" void kernel_launch(void* const* d_in, const int* in_sizes, int n_in,
                              void* d_out, int out_size) {
    const float* h   = (const float*)d_in[0];
    const float* W   = (const float*)d_in[1];
    const float* Wb  = (const float*)d_in[2];
    const float* a   = (const float*)d_in[3];
    const float* ab  = (const float*)d_in[4];
    const int*   src = (const int*)d_in[5];
    const int*   dst = (const int*)d_in[6];
    float* out = (float*)d_out;

    int n_nodes = in_sizes[0] / F;
    int n_edges = in_sizes[5];

    static cudaStream_t side = nullptr;
    static cudaEvent_t evFork = nullptr, evJoin = nullptr;
    static void* cnt_ptr = nullptr;
    if (!side) {
        cudaStreamCreateWithFlags(&side, cudaStreamNonBlocking);
        cudaEventCreateWithFlags(&evFork, cudaEventDisableTiming);
        cudaEventCreateWithFlags(&evJoin, cudaEventDisableTiming);
        cudaGetSymbolAddress(&cnt_ptr, g_cnt);
    }

    // Side stream: full CSR build incl. scatter — overlaps the wh GEMM.
    cudaEventRecord(evFork, 0);
    cudaStreamWaitEvent(side, evFork, 0);

    cudaMemsetAsync(cnt_ptr, 0, (size_t)n_nodes * sizeof(int), side);
    count_kernel<<<(n_edges + 255) / 256, 256, 0, side>>>(dst, n_edges);
    offset_kernel<<<(n_nodes + 1023) / 1024, 1024, 0, side>>>(n_nodes);
    scatter_kernel<<<(n_edges + 255) / 256, 256, 0, side>>>(src, dst, n_edges);
    cudaEventRecord(evJoin, side);

    wh_kernel<<<(n_nodes + 127) / 128, 256>>>(h, W, Wb, a, n_nodes);

    // Gather needs wh (main) + CSR/scatter (side).
    cudaStreamWaitEvent(0, evJoin, 0);
    gather_kernel<<<(n_nodes * 8 + 255) / 256, 256>>>(ab, out, n_nodes);
}